// round 2
// baseline (speedup 1.0000x reference)
#include <cuda_runtime.h>
#include <cstdint>

// ---------------------------------------------------------------------------
// GIN: two GINConv layers (eps=0), scatter-sum aggregation + 2-layer MLP each.
//   h0 = x + segsum(x[src]->dst)
//   h1 = relu(h0 @ W1a + b1a); h2 = relu(h1 @ W2a + b2a)   (outer relu fused)
//   g  = h2 + segsum(h2[src]->dst)
//   h3 = relu(g @ W1b + b1b);  out = h3 @ W2b + b2b
// ---------------------------------------------------------------------------

#define N_NODES 50000
#define D_MAX   256

// Static scratch (no allocations allowed).
__device__ float g_b0[(size_t)N_NODES * D_MAX];
__device__ float g_b1[(size_t)N_NODES * D_MAX];
__device__ float g_b2[(size_t)N_NODES * D_MAX];

// Edge-index dtype flag: 1 if the buffer is genuine int64, 0 if int32.
__device__ int g_idx_is64;

// ---------------------------------------------------------------------------
// Detect index dtype. JAX without x64 silently downgrades int64 -> int32.
// Genuine int64 node ids are all < N_NODES; int32 data reinterpreted as int64
// packs two random ids into one word -> values ~1e13. Check 64 samples.
// ---------------------------------------------------------------------------
__global__ void detect_idx_kernel(const long long* __restrict__ ei) {
    if (threadIdx.x == 0 && blockIdx.x == 0) {
        int is64 = 1;
        #pragma unroll 1
        for (int i = 0; i < 64; ++i) {
            long long v = ei[i];
            if (v < 0 || v >= (long long)N_NODES) { is64 = 0; break; }
        }
        g_idx_is64 = is64;
    }
}

// ---------------------------------------------------------------------------
// Vectorized copy (float4)
// ---------------------------------------------------------------------------
__global__ void copy_f4(const float* __restrict__ src, float* __restrict__ dst, int n4) {
    int i = blockIdx.x * blockDim.x + threadIdx.x;
    if (i < n4) {
        reinterpret_cast<float4*>(dst)[i] = reinterpret_cast<const float4*>(src)[i];
    }
}

// ---------------------------------------------------------------------------
// Scatter-add: out[dst[e]] += feat[src[e]] for all edges, feature dim D = D4*4.
// One thread per (edge, float4-chunk). Uses red.global.add.v4.f32 (no return).
// Index buffer layout: [src[0..E), dst[0..E)] in either int64 or int32.
// ---------------------------------------------------------------------------
template<int D4_LOG2>
__global__ void scatter_add_kernel(const float* __restrict__ feat,
                                   float* __restrict__ out,
                                   const void* __restrict__ ei,
                                   int E) {
    const int D4 = 1 << D4_LOG2;
    const int D  = D4 * 4;
    int t = blockIdx.x * blockDim.x + threadIdx.x;
    int e = t >> D4_LOG2;
    int c = t & (D4 - 1);
    if (e >= E) return;

    int s, d;
    if (g_idx_is64) {
        const long long* p = (const long long*)ei;
        s = (int)p[e];
        d = (int)p[e + E];
    } else {
        const int* p = (const int*)ei;
        s = p[e];
        d = p[e + E];
    }
    // Clamp defensively: a bad index becomes a wrong answer (rel_err), not a crash.
    s = min(max(s, 0), N_NODES - 1);
    d = min(max(d, 0), N_NODES - 1);

    const float4 v = *reinterpret_cast<const float4*>(feat + (size_t)s * D + c * 4);
    float* p = out + (size_t)d * D + c * 4;
    asm volatile("red.global.add.v4.f32 [%0], {%1,%2,%3,%4};"
                 :: "l"(p), "f"(v.x), "f"(v.y), "f"(v.z), "f"(v.w)
                 : "memory");
}

// ---------------------------------------------------------------------------
// SGEMM: C[M,N] = A[M,K] @ B[K,N] + bias, optional ReLU.
// Block tile 64x128, BK=16, 256 threads, 4x8 per-thread micro-tile.
// A,B,C row-major fp32. K % 16 == 0, N % 128 == 0 (true here: K in {128,256},
// N in {256,128}). M guarded.
// ---------------------------------------------------------------------------
template<bool RELU>
__global__ __launch_bounds__(256)
void sgemm_bias_kernel(const float* __restrict__ A,
                       const float* __restrict__ B,
                       const float* __restrict__ bias,
                       float* __restrict__ C,
                       int M, int K, int N) {
    constexpr int BM = 64, BN = 128, BK = 16, TM = 4, TN = 8;
    __shared__ float As[BK][BM];
    __shared__ float Bs[BK][BN];

    const int tid = threadIdx.x;
    const int bm = blockIdx.y * BM;
    const int bn = blockIdx.x * BN;

    // A tile load mapping: 64 rows x 16 cols, one float4 per thread.
    const int a_row = tid >> 2;          // 0..63
    const int a_col = (tid & 3) * 4;     // 0,4,8,12
    // B tile load mapping: 16 rows x 128 cols, two float4 per thread.
    const int b_row = tid >> 5;          // 0..7
    const int b_col = (tid & 31) * 4;    // 0..124

    const int tx = tid & 15;             // n-direction (8 cols each)
    const int ty = tid >> 4;             // m-direction (4 rows each)

    float acc[TM][TN];
    #pragma unroll
    for (int i = 0; i < TM; ++i)
        #pragma unroll
        for (int j = 0; j < TN; ++j)
            acc[i][j] = 0.0f;

    const int a_grow = bm + a_row;
    const bool a_ok = (a_grow < M);
    const float* a_ptr = A + (size_t)a_grow * K + a_col;
    const float* b_ptr0 = B + (size_t)b_row * N + bn + b_col;
    const float* b_ptr1 = B + (size_t)(b_row + 8) * N + bn + b_col;

    for (int k0 = 0; k0 < K; k0 += BK) {
        float4 av = make_float4(0.f, 0.f, 0.f, 0.f);
        if (a_ok) av = *reinterpret_cast<const float4*>(a_ptr + k0);
        As[a_col + 0][a_row] = av.x;
        As[a_col + 1][a_row] = av.y;
        As[a_col + 2][a_row] = av.z;
        As[a_col + 3][a_row] = av.w;

        float4 bv0 = *reinterpret_cast<const float4*>(b_ptr0 + (size_t)k0 * N);
        float4 bv1 = *reinterpret_cast<const float4*>(b_ptr1 + (size_t)k0 * N);
        *reinterpret_cast<float4*>(&Bs[b_row][b_col])     = bv0;
        *reinterpret_cast<float4*>(&Bs[b_row + 8][b_col]) = bv1;

        __syncthreads();

        #pragma unroll
        for (int k = 0; k < BK; ++k) {
            float ra[TM], rb[TN];
            #pragma unroll
            for (int i = 0; i < TM; ++i) ra[i] = As[k][ty * TM + i];
            #pragma unroll
            for (int j = 0; j < TN; j += 4) {
                float4 v = *reinterpret_cast<const float4*>(&Bs[k][tx * TN + j]);
                rb[j + 0] = v.x; rb[j + 1] = v.y; rb[j + 2] = v.z; rb[j + 3] = v.w;
            }
            #pragma unroll
            for (int i = 0; i < TM; ++i)
                #pragma unroll
                for (int j = 0; j < TN; ++j)
                    acc[i][j] += ra[i] * rb[j];
        }
        __syncthreads();
    }

    // Epilogue: bias (+ relu), float4 stores.
    float bvals[TN];
    #pragma unroll
    for (int j = 0; j < TN; ++j) bvals[j] = bias[bn + tx * TN + j];

    #pragma unroll
    for (int i = 0; i < TM; ++i) {
        int row = bm + ty * TM + i;
        if (row >= M) continue;
        #pragma unroll
        for (int j = 0; j < TN; j += 4) {
            float4 v;
            v.x = acc[i][j + 0] + bvals[j + 0];
            v.y = acc[i][j + 1] + bvals[j + 1];
            v.z = acc[i][j + 2] + bvals[j + 2];
            v.w = acc[i][j + 3] + bvals[j + 3];
            if (RELU) {
                v.x = fmaxf(v.x, 0.f);
                v.y = fmaxf(v.y, 0.f);
                v.z = fmaxf(v.z, 0.f);
                v.w = fmaxf(v.w, 0.f);
            }
            *reinterpret_cast<float4*>(C + (size_t)row * N + bn + tx * TN + j) = v;
        }
    }
}

// ---------------------------------------------------------------------------
// Launch
// ---------------------------------------------------------------------------
extern "C" void kernel_launch(void* const* d_in, const int* in_sizes, int n_in,
                              void* d_out, int out_size) {
    const float* x    = (const float*)d_in[0];      // [50000,128]
    const float* W1a  = (const float*)d_in[1];      // [128,256]
    const float* b1a  = (const float*)d_in[2];      // [256]
    const float* W2a  = (const float*)d_in[3];      // [256,256]
    const float* b2a  = (const float*)d_in[4];      // [256]
    const float* W1b  = (const float*)d_in[5];      // [256,256]
    const float* b1b  = (const float*)d_in[6];      // [256]
    const float* W2b  = (const float*)d_in[7];      // [256,128]
    const float* b2b  = (const float*)d_in[8];      // [128]
    const void*  ei   = d_in[9];                    // [2, E] int64 OR int32

    const int N = N_NODES;
    const int E = in_sizes[9] / 2;

    float *B0, *B1, *B2;
    cudaGetSymbolAddress((void**)&B0, g_b0);
    cudaGetSymbolAddress((void**)&B1, g_b1);
    cudaGetSymbolAddress((void**)&B2, g_b2);

    float* out = (float*)d_out;

    constexpr int BM = 64, BN = 128;
    const int gy = (N + BM - 1) / BM;   // 782

    // Detect edge-index dtype (int64 vs int32) once per launch sequence.
    detect_idx_kernel<<<1, 1>>>((const long long*)ei);

    // ---- Layer 0 ----
    // B0 = x  (d=128)
    {
        int n4 = N * 128 / 4;
        copy_f4<<<(n4 + 255) / 256, 256>>>(x, B0, n4);
    }
    // B0 += segsum(x)  (d=128 -> D4=32, log2=5)
    {
        long long work = (long long)E * 32;
        int blocks = (int)((work + 255) / 256);
        scatter_add_kernel<5><<<blocks, 256>>>(x, B0, ei, E);
    }
    // B1 = relu(B0 @ W1a + b1a)   [50000,128]@[128,256]
    sgemm_bias_kernel<true><<<dim3(256 / BN, gy), 256>>>(B0, W1a, b1a, B1, N, 128, 256);
    // B2 = relu(B1 @ W2a + b2a)   [50000,256]@[256,256]  (outer relu fused)
    sgemm_bias_kernel<true><<<dim3(256 / BN, gy), 256>>>(B1, W2a, b2a, B2, N, 256, 256);

    // ---- Layer 1 ----
    // B0 = B2  (d=256)
    {
        int n4 = N * 256 / 4;
        copy_f4<<<(n4 + 255) / 256, 256>>>(B2, B0, n4);
    }
    // B0 += segsum(B2)  (d=256 -> D4=64, log2=6)
    {
        long long work = (long long)E * 64;
        int blocks = (int)((work + 255) / 256);
        scatter_add_kernel<6><<<blocks, 256>>>(B2, B0, ei, E);
    }
    // B1 = relu(B0 @ W1b + b1b)   [50000,256]@[256,256]
    sgemm_bias_kernel<true><<<dim3(256 / BN, gy), 256>>>(B0, W1b, b1b, B1, N, 256, 256);
    // out = B1 @ W2b + b2b        [50000,256]@[256,128], no relu
    sgemm_bias_kernel<false><<<dim3(128 / BN, gy), 256>>>(B1, W2b, b2b, out, N, 256, 128);
}

// round 3
// speedup vs baseline: 1.1608x; 1.1608x over previous
#include <cuda_runtime.h>
#include <cstdint>

// ---------------------------------------------------------------------------
// GIN: two GINConv layers (eps=0), scatter-sum aggregation + 2-layer MLP each.
// ---------------------------------------------------------------------------

#define N_NODES 50000
#define D_MAX   256

// Static scratch (no allocations allowed).
__device__ float g_b0[(size_t)N_NODES * D_MAX];
__device__ float g_b1[(size_t)N_NODES * D_MAX];
__device__ float g_b2[(size_t)N_NODES * D_MAX];

// Edge-index dtype flag: 1 if the buffer is genuine int64, 0 if int32.
__device__ int g_idx_is64;

__global__ void detect_idx_kernel(const long long* __restrict__ ei) {
    if (threadIdx.x == 0 && blockIdx.x == 0) {
        int is64 = 1;
        #pragma unroll 1
        for (int i = 0; i < 64; ++i) {
            long long v = ei[i];
            if (v < 0 || v >= (long long)N_NODES) { is64 = 0; break; }
        }
        g_idx_is64 = is64;
    }
}

__global__ void copy_f4(const float* __restrict__ src, float* __restrict__ dst, int n4) {
    int i = blockIdx.x * blockDim.x + threadIdx.x;
    if (i < n4) {
        reinterpret_cast<float4*>(dst)[i] = reinterpret_cast<const float4*>(src)[i];
    }
}

// ---------------------------------------------------------------------------
// Scatter-add: out[dst[e]] += feat[src[e]], feature dim D = 4 << D4_LOG2.
// One thread per (edge, float4-chunk); red.global.add.v4.f32 (no return trip).
// ---------------------------------------------------------------------------
template<int D4_LOG2>
__global__ void scatter_add_kernel(const float* __restrict__ feat,
                                   float* __restrict__ out,
                                   const void* __restrict__ ei,
                                   int E) {
    const int D4 = 1 << D4_LOG2;
    const int D  = D4 * 4;
    int t = blockIdx.x * blockDim.x + threadIdx.x;
    int e = t >> D4_LOG2;
    int c = t & (D4 - 1);
    if (e >= E) return;

    int s, d;
    if (g_idx_is64) {
        const long long* p = (const long long*)ei;
        s = (int)p[e];
        d = (int)p[e + E];
    } else {
        const int* p = (const int*)ei;
        s = p[e];
        d = p[e + E];
    }
    s = min(max(s, 0), N_NODES - 1);
    d = min(max(d, 0), N_NODES - 1);

    const float4 v = *reinterpret_cast<const float4*>(feat + (size_t)s * D + c * 4);
    float* p = out + (size_t)d * D + c * 4;
    asm volatile("red.global.add.v4.f32 [%0], {%1,%2,%3,%4};"
                 :: "l"(p), "f"(v.x), "f"(v.y), "f"(v.z), "f"(v.w)
                 : "memory");
}

// ---------------------------------------------------------------------------
// SGEMM: C[M,N] = A[M,K] @ B[K,N] + bias, optional ReLU.
// 128x128 block tile, BK=8, 256 threads, 8x8 micro-tile.
// Double-buffered smem + register-staged global prefetch.
// Requires K % 8 == 0, N % 128 == 0 (true: K in {128,256}, N in {256,128}).
// ---------------------------------------------------------------------------
template<bool RELU>
__global__ __launch_bounds__(256)
void sgemm_bias_kernel(const float* __restrict__ A,
                       const float* __restrict__ B,
                       const float* __restrict__ bias,
                       float* __restrict__ C,
                       int M, int K, int N) {
    constexpr int BM = 128, BN = 128, BK = 8, TM = 8, TN = 8;
    __shared__ float As[2][BK][BM];   // transposed A tile
    __shared__ float Bs[2][BK][BN];

    const int tid = threadIdx.x;
    const int bm = blockIdx.y * BM;
    const int bn = blockIdx.x * BN;

    // A tile: 128 rows x 8 cols, one float4 per thread.
    const int a_row = tid >> 1;          // 0..127
    const int a_col = (tid & 1) * 4;     // 0 or 4
    // B tile: 8 rows x 128 cols, one float4 per thread.
    const int b_row = tid >> 5;          // 0..7
    const int b_col = (tid & 31) * 4;    // 0..124

    const int tx = tid & 15;             // n-direction
    const int ty = tid >> 4;             // m-direction

    float acc[TM][TN];
    #pragma unroll
    for (int i = 0; i < TM; ++i)
        #pragma unroll
        for (int j = 0; j < TN; ++j)
            acc[i][j] = 0.0f;

    const int a_grow = bm + a_row;
    const bool a_ok = (a_grow < M);
    const float* a_ptr = A + (size_t)a_grow * K + a_col;
    const float* b_ptr = B + (size_t)b_row * N + bn + b_col;

    const int n_tiles = K / BK;

    // Preload tile 0.
    float4 av = make_float4(0.f, 0.f, 0.f, 0.f);
    if (a_ok) av = *reinterpret_cast<const float4*>(a_ptr);
    float4 bv = *reinterpret_cast<const float4*>(b_ptr);

    As[0][a_col + 0][a_row] = av.x;
    As[0][a_col + 1][a_row] = av.y;
    As[0][a_col + 2][a_row] = av.z;
    As[0][a_col + 3][a_row] = av.w;
    *reinterpret_cast<float4*>(&Bs[0][b_row][b_col]) = bv;
    __syncthreads();

    for (int t = 0; t < n_tiles; ++t) {
        const int buf = t & 1;

        // Prefetch next tile into registers.
        if (t + 1 < n_tiles) {
            av = make_float4(0.f, 0.f, 0.f, 0.f);
            if (a_ok) av = *reinterpret_cast<const float4*>(a_ptr + (t + 1) * BK);
            bv = *reinterpret_cast<const float4*>(b_ptr + (size_t)(t + 1) * BK * N);
        }

        // Compute on current buffer.
        #pragma unroll
        for (int k = 0; k < BK; ++k) {
            float ra[TM], rb[TN];
            float4 a0 = *reinterpret_cast<const float4*>(&As[buf][k][ty * TM]);
            float4 a1 = *reinterpret_cast<const float4*>(&As[buf][k][ty * TM + 4]);
            ra[0] = a0.x; ra[1] = a0.y; ra[2] = a0.z; ra[3] = a0.w;
            ra[4] = a1.x; ra[5] = a1.y; ra[6] = a1.z; ra[7] = a1.w;
            float4 b0 = *reinterpret_cast<const float4*>(&Bs[buf][k][tx * TN]);
            float4 b1 = *reinterpret_cast<const float4*>(&Bs[buf][k][tx * TN + 4]);
            rb[0] = b0.x; rb[1] = b0.y; rb[2] = b0.z; rb[3] = b0.w;
            rb[4] = b1.x; rb[5] = b1.y; rb[6] = b1.z; rb[7] = b1.w;
            #pragma unroll
            for (int i = 0; i < TM; ++i)
                #pragma unroll
                for (int j = 0; j < TN; ++j)
                    acc[i][j] += ra[i] * rb[j];
        }

        // Stage prefetched tile into the other buffer.
        if (t + 1 < n_tiles) {
            const int nb = buf ^ 1;
            As[nb][a_col + 0][a_row] = av.x;
            As[nb][a_col + 1][a_row] = av.y;
            As[nb][a_col + 2][a_row] = av.z;
            As[nb][a_col + 3][a_row] = av.w;
            *reinterpret_cast<float4*>(&Bs[nb][b_row][b_col]) = bv;
            __syncthreads();
        }
    }

    // Epilogue: bias (+ relu), float4 stores.
    float bvals[TN];
    #pragma unroll
    for (int j = 0; j < TN; ++j) bvals[j] = bias[bn + tx * TN + j];

    #pragma unroll
    for (int i = 0; i < TM; ++i) {
        int row = bm + ty * TM + i;
        if (row >= M) continue;
        #pragma unroll
        for (int j = 0; j < TN; j += 4) {
            float4 v;
            v.x = acc[i][j + 0] + bvals[j + 0];
            v.y = acc[i][j + 1] + bvals[j + 1];
            v.z = acc[i][j + 2] + bvals[j + 2];
            v.w = acc[i][j + 3] + bvals[j + 3];
            if (RELU) {
                v.x = fmaxf(v.x, 0.f);
                v.y = fmaxf(v.y, 0.f);
                v.z = fmaxf(v.z, 0.f);
                v.w = fmaxf(v.w, 0.f);
            }
            *reinterpret_cast<float4*>(C + (size_t)row * N + bn + tx * TN + j) = v;
        }
    }
}

// ---------------------------------------------------------------------------
// Launch
// ---------------------------------------------------------------------------
extern "C" void kernel_launch(void* const* d_in, const int* in_sizes, int n_in,
                              void* d_out, int out_size) {
    const float* x    = (const float*)d_in[0];      // [50000,128]
    const float* W1a  = (const float*)d_in[1];      // [128,256]
    const float* b1a  = (const float*)d_in[2];      // [256]
    const float* W2a  = (const float*)d_in[3];      // [256,256]
    const float* b2a  = (const float*)d_in[4];      // [256]
    const float* W1b  = (const float*)d_in[5];      // [256,256]
    const float* b1b  = (const float*)d_in[6];      // [256]
    const float* W2b  = (const float*)d_in[7];      // [256,128]
    const float* b2b  = (const float*)d_in[8];      // [128]
    const void*  ei   = d_in[9];                    // [2, E] int64 OR int32

    const int N = N_NODES;
    const int E = in_sizes[9] / 2;

    float *B0, *B1, *B2;
    cudaGetSymbolAddress((void**)&B0, g_b0);
    cudaGetSymbolAddress((void**)&B1, g_b1);
    cudaGetSymbolAddress((void**)&B2, g_b2);

    float* out = (float*)d_out;

    constexpr int BM = 128, BN = 128;
    const int gy = (N + BM - 1) / BM;   // 391

    detect_idx_kernel<<<1, 1>>>((const long long*)ei);

    // ---- Layer 0 ----
    {
        int n4 = N * 128 / 4;
        copy_f4<<<(n4 + 255) / 256, 256>>>(x, B0, n4);
    }
    {
        long long work = (long long)E * 32;
        int blocks = (int)((work + 255) / 256);
        scatter_add_kernel<5><<<blocks, 256>>>(x, B0, ei, E);
    }
    sgemm_bias_kernel<true><<<dim3(256 / BN, gy), 256>>>(B0, W1a, b1a, B1, N, 128, 256);
    sgemm_bias_kernel<true><<<dim3(256 / BN, gy), 256>>>(B1, W2a, b2a, B2, N, 256, 256);

    // ---- Layer 1 ----
    {
        int n4 = N * 256 / 4;
        copy_f4<<<(n4 + 255) / 256, 256>>>(B2, B0, n4);
    }
    {
        long long work = (long long)E * 64;
        int blocks = (int)((work + 255) / 256);
        scatter_add_kernel<6><<<blocks, 256>>>(B2, B0, ei, E);
    }
    sgemm_bias_kernel<true><<<dim3(256 / BN, gy), 256>>>(B0, W1b, b1b, B1, N, 256, 256);
    sgemm_bias_kernel<false><<<dim3(128 / BN, gy), 256>>>(B1, W2b, b2b, out, N, 256, 128);
}

// round 5
// speedup vs baseline: 1.8681x; 1.6092x over previous
#include <cuda_runtime.h>
#include <cuda_bf16.h>
#include <cstdint>

// ---------------------------------------------------------------------------
// GIN on GB300 (compute_103-portable): scatter-sum (fp32 red.global) +
// bf16 error-compensated split GEMMs on mma.sync tensor cores.
//   C = Ahi@Bhi + Ahi@Blo + Alo@Bhi  (fp32 accumulate)  ~ fp32 GEMM, ~1e-5
// ---------------------------------------------------------------------------

#define N_NODES 50000
#define M_PAD   50048      // 128 * 391
#define D_MAX   256

// Static scratch.
__device__ float g_f0[(size_t)M_PAD * D_MAX];          // fp32 aggregate
__device__ float g_f1[(size_t)M_PAD * D_MAX];          // fp32 h2
__device__ __nv_bfloat16 g_ahi[(size_t)M_PAD * D_MAX];
__device__ __nv_bfloat16 g_alo[(size_t)M_PAD * D_MAX];
__device__ __nv_bfloat16 g_bhi[(size_t)M_PAD * D_MAX];
__device__ __nv_bfloat16 g_blo[(size_t)M_PAD * D_MAX];
__device__ __nv_bfloat16 g_wthi[4][256 * 256];         // transposed weights [N][K]
__device__ __nv_bfloat16 g_wtlo[4][256 * 256];
__device__ int g_idx_is64;

// ---------------------------------------------------------------------------
// PTX helpers (portable: ldmatrix + mma.sync, sm_80+)
// ---------------------------------------------------------------------------
static __device__ __forceinline__ uint32_t smem_u32(const void* p) {
    uint32_t a;
    asm("{ .reg .u64 t; cvta.to.shared.u64 t, %1; cvt.u32.u64 %0, t; }" : "=r"(a) : "l"(p));
    return a;
}

static __device__ __forceinline__ void ldsm_x4(uint32_t* r, uint32_t addr) {
    asm volatile("ldmatrix.sync.aligned.m8n8.x4.shared.b16 {%0,%1,%2,%3}, [%4];"
                 : "=r"(r[0]), "=r"(r[1]), "=r"(r[2]), "=r"(r[3]) : "r"(addr));
}

static __device__ __forceinline__ void mma16816(float* c, const uint32_t* a, const uint32_t* b) {
    asm volatile("mma.sync.aligned.m16n8k16.row.col.f32.bf16.bf16.f32 "
                 "{%0,%1,%2,%3}, {%4,%5,%6,%7}, {%8,%9}, {%0,%1,%2,%3};"
                 : "+f"(c[0]), "+f"(c[1]), "+f"(c[2]), "+f"(c[3])
                 : "r"(a[0]), "r"(a[1]), "r"(a[2]), "r"(a[3]), "r"(b[0]), "r"(b[1]));
}

// ---------------------------------------------------------------------------
// Small utility kernels
// ---------------------------------------------------------------------------
__global__ void detect_idx_kernel(const long long* __restrict__ ei) {
    if (threadIdx.x == 0 && blockIdx.x == 0) {
        int is64 = 1;
        #pragma unroll 1
        for (int i = 0; i < 64; ++i) {
            long long v = ei[i];
            if (v < 0 || v >= (long long)N_NODES) { is64 = 0; break; }
        }
        g_idx_is64 = is64;
    }
}

__global__ void copy_f4(const float* __restrict__ src, float* __restrict__ dst, int n4) {
    int i = blockIdx.x * blockDim.x + threadIdx.x;
    if (i < n4) reinterpret_cast<float4*>(dst)[i] = reinterpret_cast<const float4*>(src)[i];
}

// Transpose + split a weight: W[K,N] fp32 -> Wt_hi/Wt_lo [N,K] bf16.
__global__ void prep_weight(const float* __restrict__ W,
                            __nv_bfloat16* __restrict__ hi,
                            __nv_bfloat16* __restrict__ lo, int K, int N) {
    int i = blockIdx.x * blockDim.x + threadIdx.x;    // over N*K
    if (i >= N * K) return;
    int n = i / K, k = i % K;
    float v = W[(size_t)k * N + n];
    __nv_bfloat16 h = __float2bfloat16(v);
    hi[i] = h;
    lo[i] = __float2bfloat16(v - __bfloat162float(h));
}

// Split node features fp32 -> hi/lo bf16, zero padding rows.
__global__ void split_feats4(const float4* __restrict__ A,
                             __nv_bfloat16* __restrict__ hi,
                             __nv_bfloat16* __restrict__ lo,
                             int n4_valid, int n4_total) {
    int i = blockIdx.x * blockDim.x + threadIdx.x;
    if (i >= n4_total) return;
    float4 v = (i < n4_valid) ? A[i] : make_float4(0.f, 0.f, 0.f, 0.f);
    __nv_bfloat16 h[4], l[4];
    float vv[4] = {v.x, v.y, v.z, v.w};
    #pragma unroll
    for (int j = 0; j < 4; ++j) {
        h[j] = __float2bfloat16(vv[j]);
        l[j] = __float2bfloat16(vv[j] - __bfloat162float(h[j]));
    }
    *reinterpret_cast<uint2*>(hi + (size_t)i * 4) = *reinterpret_cast<uint2*>(h);
    *reinterpret_cast<uint2*>(lo + (size_t)i * 4) = *reinterpret_cast<uint2*>(l);
}

// ---------------------------------------------------------------------------
// Scatter-add (fp32, red.global.add.v4)
// ---------------------------------------------------------------------------
template<int D4_LOG2>
__global__ void scatter_add_kernel(const float* __restrict__ feat,
                                   float* __restrict__ out,
                                   const void* __restrict__ ei,
                                   int E) {
    const int D4 = 1 << D4_LOG2;
    const int D  = D4 * 4;
    int t = blockIdx.x * blockDim.x + threadIdx.x;
    int e = t >> D4_LOG2;
    int c = t & (D4 - 1);
    if (e >= E) return;

    int s, d;
    if (g_idx_is64) {
        const long long* p = (const long long*)ei;
        s = (int)p[e];
        d = (int)p[e + E];
    } else {
        const int* p = (const int*)ei;
        s = p[e];
        d = p[e + E];
    }
    s = min(max(s, 0), N_NODES - 1);
    d = min(max(d, 0), N_NODES - 1);

    const float4 v = *reinterpret_cast<const float4*>(feat + (size_t)s * D + c * 4);
    float* p = out + (size_t)d * D + c * 4;
    asm volatile("red.global.add.v4.f32 [%0], {%1,%2,%3,%4};"
                 :: "l"(p), "f"(v.x), "f"(v.y), "f"(v.z), "f"(v.w)
                 : "memory");
}

// ---------------------------------------------------------------------------
// mma.sync GEMM: C[M,N] = A[M,K]@B^T  (B stored transposed [N,K]).
// A,B as bf16 hi/lo splits; fp32 accumulate of 3 split products.
// CTA tile 128x128, BK=32, 256 threads (8 warps, 2x4), warp tile 64x32.
// EPI: 0 = fp32 out (no relu), 1 = relu -> bf16 hi/lo split, 2 = relu -> fp32.
// A/B row loads unguarded (buffers padded to M_PAD / weights full).
// ---------------------------------------------------------------------------
template<int EPI>
__global__ __launch_bounds__(256)
void mma_gemm(const __nv_bfloat16* __restrict__ Ahi, const __nv_bfloat16* __restrict__ Alo,
              const __nv_bfloat16* __restrict__ Bth, const __nv_bfloat16* __restrict__ Btl,
              const float* __restrict__ bias,
              float* __restrict__ outf,
              __nv_bfloat16* __restrict__ ohi, __nv_bfloat16* __restrict__ olo,
              int M, int K, int N) {
    constexpr int BM = 128, BK = 32, LDS = BK + 8;   // pad -> conflict-free ldmatrix
    __shared__ __nv_bfloat16 As[2][BM][LDS];
    __shared__ __nv_bfloat16 Bs[2][BM][LDS];

    const int tid  = threadIdx.x;
    const int wid  = tid >> 5;
    const int lane = tid & 31;
    const int bm = blockIdx.y * 128;
    const int bn = blockIdx.x * 128;

    const int wm = (wid >> 2) * 64;   // warp m offset: 0 or 64
    const int wn = (wid & 3) * 32;    // warp n offset: 0,32,64,96

    const uint32_t as0 = smem_u32(&As[0][0][0]);
    const uint32_t as1 = smem_u32(&As[1][0][0]);
    const uint32_t bs0 = smem_u32(&Bs[0][0][0]);
    const uint32_t bs1 = smem_u32(&Bs[1][0][0]);

    // ldmatrix lane mapping (shared by A and B x4 loads):
    const int lane_r = lane & 15;          // row within 16-row group
    const int lane_c = (lane >> 4) * 8;    // k-half

    float acc[4][4][4];
    #pragma unroll
    for (int mf = 0; mf < 4; ++mf)
        #pragma unroll
        for (int nf = 0; nf < 4; ++nf)
            #pragma unroll
            for (int c = 0; c < 4; ++c)
                acc[mf][nf][c] = 0.0f;

    // Global load mapping: 512 chunks of 8 bf16 per tile (2 iters x 256 thr).
    const int g_row0 = tid >> 2;                 // 0..63
    const int g_col  = (tid & 3) * 8;            // 0,8,16,24

    const int ktiles = K >> 5;
    for (int kt = 0; kt < ktiles; ++kt) {
        const int k0 = kt << 5;
        #pragma unroll
        for (int it = 0; it < 2; ++it) {
            const int row = g_row0 + it * 64;
            const size_t ga = (size_t)(bm + row) * K + k0 + g_col;
            const size_t gb = (size_t)(bn + row) * K + k0 + g_col;
            *reinterpret_cast<uint4*>(&As[0][row][g_col]) = *reinterpret_cast<const uint4*>(Ahi + ga);
            *reinterpret_cast<uint4*>(&As[1][row][g_col]) = *reinterpret_cast<const uint4*>(Alo + ga);
            *reinterpret_cast<uint4*>(&Bs[0][row][g_col]) = *reinterpret_cast<const uint4*>(Bth + gb);
            *reinterpret_cast<uint4*>(&Bs[1][row][g_col]) = *reinterpret_cast<const uint4*>(Btl + gb);
        }
        __syncthreads();

        #pragma unroll
        for (int ks = 0; ks < 2; ++ks) {
            const int kb = ks * 16;
            const uint32_t a_off = (uint32_t)(kb + lane_c) * 2;

            uint32_t ah[4][4], al[4][4];
            #pragma unroll
            for (int mf = 0; mf < 4; ++mf) {
                const uint32_t ro = (uint32_t)((wm + mf * 16 + lane_r) * LDS) * 2;
                ldsm_x4(ah[mf], as0 + ro + a_off);
                ldsm_x4(al[mf], as1 + ro + a_off);
            }
            uint32_t bh[4][2], bl[4][2];
            #pragma unroll
            for (int np = 0; np < 2; ++np) {     // n-frag pairs
                const uint32_t ro = (uint32_t)((wn + np * 16 + lane_r) * LDS) * 2;
                uint32_t r[4];
                ldsm_x4(r, bs0 + ro + a_off);
                bh[np * 2 + 0][0] = r[0]; bh[np * 2 + 0][1] = r[2];
                bh[np * 2 + 1][0] = r[1]; bh[np * 2 + 1][1] = r[3];
                ldsm_x4(r, bs1 + ro + a_off);
                bl[np * 2 + 0][0] = r[0]; bl[np * 2 + 0][1] = r[2];
                bl[np * 2 + 1][0] = r[1]; bl[np * 2 + 1][1] = r[3];
            }

            #pragma unroll
            for (int mf = 0; mf < 4; ++mf)
                #pragma unroll
                for (int nf = 0; nf < 4; ++nf) {
                    mma16816(acc[mf][nf], ah[mf], bh[nf]);
                    mma16816(acc[mf][nf], ah[mf], bl[nf]);
                    mma16816(acc[mf][nf], al[mf], bh[nf]);
                }
        }
        __syncthreads();
    }

    // Epilogue. Thread t of each warp owns rows (gr, gr+8), cols 2*(t%4)+{0,1}
    // within each m16n8 fragment.
    const int gr = lane >> 2;
    const int gc = (lane & 3) * 2;
    #pragma unroll
    for (int mf = 0; mf < 4; ++mf) {
        const int row0 = bm + wm + mf * 16 + gr;
        const int row1 = row0 + 8;
        #pragma unroll
        for (int nf = 0; nf < 4; ++nf) {
            const int col = bn + wn + nf * 8 + gc;
            const float bz0 = bias[col], bz1 = bias[col + 1];
            float v00 = acc[mf][nf][0] + bz0, v01 = acc[mf][nf][1] + bz1;
            float v10 = acc[mf][nf][2] + bz0, v11 = acc[mf][nf][3] + bz1;
            if (EPI != 0) {
                v00 = fmaxf(v00, 0.f); v01 = fmaxf(v01, 0.f);
                v10 = fmaxf(v10, 0.f); v11 = fmaxf(v11, 0.f);
            }
            if (EPI == 1) {
                if (row0 < M) {
                    __nv_bfloat16 h0 = __float2bfloat16(v00), h1 = __float2bfloat16(v01);
                    __nv_bfloat162 hh; hh.x = h0; hh.y = h1;
                    __nv_bfloat162 ll;
                    ll.x = __float2bfloat16(v00 - __bfloat162float(h0));
                    ll.y = __float2bfloat16(v01 - __bfloat162float(h1));
                    *reinterpret_cast<__nv_bfloat162*>(ohi + (size_t)row0 * N + col) = hh;
                    *reinterpret_cast<__nv_bfloat162*>(olo + (size_t)row0 * N + col) = ll;
                }
                if (row1 < M) {
                    __nv_bfloat16 h0 = __float2bfloat16(v10), h1 = __float2bfloat16(v11);
                    __nv_bfloat162 hh; hh.x = h0; hh.y = h1;
                    __nv_bfloat162 ll;
                    ll.x = __float2bfloat16(v10 - __bfloat162float(h0));
                    ll.y = __float2bfloat16(v11 - __bfloat162float(h1));
                    *reinterpret_cast<__nv_bfloat162*>(ohi + (size_t)row1 * N + col) = hh;
                    *reinterpret_cast<__nv_bfloat162*>(olo + (size_t)row1 * N + col) = ll;
                }
            } else {
                if (row0 < M) {
                    float2 v; v.x = v00; v.y = v01;
                    *reinterpret_cast<float2*>(outf + (size_t)row0 * N + col) = v;
                }
                if (row1 < M) {
                    float2 v; v.x = v10; v.y = v11;
                    *reinterpret_cast<float2*>(outf + (size_t)row1 * N + col) = v;
                }
            }
        }
    }
}

// ---------------------------------------------------------------------------
// Launch
// ---------------------------------------------------------------------------
extern "C" void kernel_launch(void* const* d_in, const int* in_sizes, int n_in,
                              void* d_out, int out_size) {
    const float* x    = (const float*)d_in[0];
    const float* W1a  = (const float*)d_in[1];
    const float* b1a  = (const float*)d_in[2];
    const float* W2a  = (const float*)d_in[3];
    const float* b2a  = (const float*)d_in[4];
    const float* W1b  = (const float*)d_in[5];
    const float* b1b  = (const float*)d_in[6];
    const float* W2b  = (const float*)d_in[7];
    const float* b2b  = (const float*)d_in[8];
    const void*  ei   = d_in[9];

    const int M = N_NODES;
    const int E = in_sizes[9] / 2;

    float *F0, *F1;
    __nv_bfloat16 *AHI, *ALO, *BHI, *BLO, *WTH, *WTL;
    cudaGetSymbolAddress((void**)&F0, g_f0);
    cudaGetSymbolAddress((void**)&F1, g_f1);
    cudaGetSymbolAddress((void**)&AHI, g_ahi);
    cudaGetSymbolAddress((void**)&ALO, g_alo);
    cudaGetSymbolAddress((void**)&BHI, g_bhi);
    cudaGetSymbolAddress((void**)&BLO, g_blo);
    cudaGetSymbolAddress((void**)&WTH, g_wthi);
    cudaGetSymbolAddress((void**)&WTL, g_wtlo);

    float* out = (float*)d_out;

    const int GY = M_PAD / 128;   // 391

    detect_idx_kernel<<<1, 1>>>((const long long*)ei);

    // Weight prep: Wt[N][K] hi/lo splits, 4 slots.
    prep_weight<<<(256 * 128 + 255) / 256, 256>>>(W1a, WTH + 0 * 65536, WTL + 0 * 65536, 128, 256);
    prep_weight<<<(256 * 256 + 255) / 256, 256>>>(W2a, WTH + 1 * 65536, WTL + 1 * 65536, 256, 256);
    prep_weight<<<(256 * 256 + 255) / 256, 256>>>(W1b, WTH + 2 * 65536, WTL + 2 * 65536, 256, 256);
    prep_weight<<<(128 * 256 + 255) / 256, 256>>>(W2b, WTH + 3 * 65536, WTL + 3 * 65536, 256, 128);

    // ---- Layer 0 ----
    {
        int n4 = M * 128 / 4;
        copy_f4<<<(n4 + 255) / 256, 256>>>(x, F0, n4);
        long long work = (long long)E * 32;
        scatter_add_kernel<5><<<(int)((work + 255) / 256), 256>>>(x, F0, ei, E);
        int n4v = M * 128 / 4, n4t = M_PAD * 128 / 4;
        split_feats4<<<(n4t + 255) / 256, 256>>>((const float4*)F0, AHI, ALO, n4v, n4t);
    }
    // h1 = relu(agg0 @ W1a + b1a) -> split   [50000,128]@[128,256]
    mma_gemm<1><<<dim3(2, GY), 256>>>(AHI, ALO, WTH + 0 * 65536, WTL + 0 * 65536,
                                      b1a, nullptr, BHI, BLO, M, 128, 256);
    // h2 = relu(h1 @ W2a + b2a) -> fp32      [50000,256]@[256,256]
    mma_gemm<2><<<dim3(2, GY), 256>>>(BHI, BLO, WTH + 1 * 65536, WTL + 1 * 65536,
                                      b2a, F1, nullptr, nullptr, M, 256, 256);

    // ---- Layer 1 ----
    {
        int n4 = M * 256 / 4;
        copy_f4<<<(n4 + 255) / 256, 256>>>(F1, F0, n4);
        long long work = (long long)E * 64;
        scatter_add_kernel<6><<<(int)((work + 255) / 256), 256>>>(F1, F0, ei, E);
        int n4v = M * 256 / 4, n4t = M_PAD * 256 / 4;
        split_feats4<<<(n4t + 255) / 256, 256>>>((const float4*)F0, AHI, ALO, n4v, n4t);
    }
    // h3 = relu(agg1 @ W1b + b1b) -> split   [50000,256]@[256,256]
    mma_gemm<1><<<dim3(2, GY), 256>>>(AHI, ALO, WTH + 2 * 65536, WTL + 2 * 65536,
                                      b1b, nullptr, BHI, BLO, M, 256, 256);
    // out = h3 @ W2b + b2b                   [50000,256]@[256,128]
    mma_gemm<0><<<dim3(1, GY), 256>>>(BHI, BLO, WTH + 3 * 65536, WTL + 3 * 65536,
                                      b2b, out, nullptr, nullptr, M, 256, 128);
}